// round 10
// baseline (speedup 1.0000x reference)
#include <cuda_runtime.h>

// Problem constants (from reference)
#define G_ 4096
#define U_ 50
#define M_ 20
#define D_ 64
#define S_ 64
#define FACTOR_ 0.5f

// Half-group per CTA: grid = 2*G, 25 users per CTA, one user per half-warp slot.
// 448 threads = 14 warps = 28 slots (25 active). __launch_bounds__(448,2) gives
// ptxas a 73-register budget so the 10-deep gather batch can stay in flight.
#define NWARPS 14
#define NTHREADS (NWARPS * 32)   // 448
#define UPC 25                   // users per CTA
#define MB 10                    // gather batch depth

// Inter-CTA partials: [2*G][D] fp32 (2 MB static scratch, no allocation).
__device__ float g_part[2 * G_ * D_];

__global__ __launch_bounds__(NTHREADS, 2)
void group_embedding_main(const int*   __restrict__ group_user,      // [G,U]
                          const int*   __restrict__ behavior_ids,    // [G,U,M]
                          const float* __restrict__ behavior_counts, // [G,U,M]
                          const int*   __restrict__ target_user,     // [G]
                          const float* __restrict__ similarity_vec,  // [100000,S]
                          const float* __restrict__ user_emb_w,      // [100000,D]
                          const float* __restrict__ item_emb_w)      // [100000,D]
{
    const int b    = blockIdx.x;
    const int g    = b >> 1;
    const int hsel = b & 1;          // which 25-user half of the group
    const int tid  = threadIdx.x;
    const int warp = tid >> 5;
    const int lane = tid & 31;
    const int half = lane >> 4;      // half-warp id
    const int hl   = lane & 15;      // owns dims 4*hl..4*hl+3
    const int slot = warp * 2 + half;   // 0..27; active if < UPC
    const bool active = (slot < UPC);
    // Exact mask of this 16-lane half; every lane in a half is uniformly
    // active or inactive, so half-masked shuffles are deadlock-free.
    const unsigned hmask = 0xffffu << (16 * half);

    __shared__ __align__(16) float  partials[UPC][D_];    // 6.4KB
    __shared__ __align__(16) float  red[7][D_];           // 1.75KB
    __shared__ __align__(16) float2 wbeh[NWARPS][2 * M_]; // 7KB

    // ---- Per-warp staging of this warp's (up to 2) users' pairs ----
    {
        const int start = warp * (2 * M_);             // pair index within CTA
        const int npair = UPC * M_ - start;            // 40, or 20 for warp 12
        const int base  = (g * U_ + hsel * UPC) * M_ + start;
        if (lane < npair)
            wbeh[warp][lane] = make_float2(__int_as_float(behavior_ids[base + lane]),
                                           behavior_counts[base + lane]);
        if (lane + 32 < npair)
            wbeh[warp][32 + lane] =
                make_float2(__int_as_float(behavior_ids[base + 32 + lane]),
                            behavior_counts[base + 32 + lane]);
    }
    __syncwarp();   // convergent: wbeh slice visible to whole warp

    float4 acc = make_float4(0.f, 0.f, 0.f, 0.f);

    if (active) {
        const int u   = hsel * UPC + slot;
        const int uid = group_user[g * U_ + u];

        // Early loads to overlap the gather chain.
        const float4 ue = *reinterpret_cast<const float4*>(
            user_emb_w + (size_t)uid * D_ + 4 * hl);

        const int tgt = target_user[g];
        const float4 tsim = *reinterpret_cast<const float4*>(
            similarity_vec + (size_t)tgt * S_ + 4 * hl);
        const float4 osim = *reinterpret_cast<const float4*>(
            similarity_vec + (size_t)uid * S_ + 4 * hl);
        float dot = tsim.x * osim.x + tsim.y * osim.y
                  + tsim.z * osim.z + tsim.w * osim.w;
        #pragma unroll
        for (int o = 8; o; o >>= 1)
            dot += __shfl_xor_sync(hmask, dot, o);
        const float sim = FACTOR_ * dot;

        // MB-deep batched gathers: MB independent LDG.128s in flight.
        float4 ub = make_float4(0.f, 0.f, 0.f, 0.f);
        const int bbase = half * M_;
        #pragma unroll
        for (int mb = 0; mb < M_; mb += MB) {
            float  c[MB];
            float4 e[MB];
            #pragma unroll
            for (int j = 0; j < MB; j++) {
                const float2 p = wbeh[warp][bbase + mb + j];
                c[j] = p.y;
                e[j] = *reinterpret_cast<const float4*>(
                    item_emb_w + (size_t)__float_as_int(p.x) * D_ + 4 * hl);
            }
            #pragma unroll
            for (int j = 0; j < MB; j++) {
                ub.x += e[j].x * c[j];
                ub.y += e[j].y * c[j];
                ub.z += e[j].z * c[j];
                ub.w += e[j].w * c[j];
            }
        }

        acc.x = ub.x * ue.x * sim;
        acc.y = ub.y * ue.y * sim;
        acc.z = ub.z * ue.z * sim;
        acc.w = ub.w * ue.w * sim;

        *reinterpret_cast<float4*>(&partials[slot][4 * hl]) = acc;
    }
    __syncthreads();

    // ---- Two-stage deterministic reduce over 25 slots ----
    // Stage 1: 448 threads = 7 rows x 64 dims; row r sums slots r, r+7, r+14, r+21.
    {
        const int d = tid & 63;
        const int r = tid >> 6;      // 0..6
        float s = 0.f;
        #pragma unroll
        for (int p = r; p < UPC; p += 7)
            s += partials[p][d];
        red[r][d] = s;
    }
    __syncthreads();

    // Stage 2: 64 threads fold the 7 rows into the inter-CTA scratch.
    if (tid < D_) {
        float s = 0.f;
        #pragma unroll
        for (int r = 0; r < 7; r++)
            s += red[r][tid];
        g_part[(size_t)b * D_ + tid] = s;
    }
}

// Fold the two half-group partials into the final output.
__global__ __launch_bounds__(256)
void group_embedding_reduce(float* __restrict__ out)   // [G,D]
{
    const int idx = blockIdx.x * 256 + threadIdx.x;    // 0 .. G*D-1
    const int g = idx >> 6;
    const int d = idx & 63;
    out[idx] = g_part[(size_t)(2 * g) * D_ + d]
             + g_part[(size_t)(2 * g + 1) * D_ + d];
}

extern "C" void kernel_launch(void* const* d_in, const int* in_sizes, int n_in,
                              void* d_out, int out_size) {
    const int*   group_user      = (const int*)  d_in[0];
    const int*   behavior_ids    = (const int*)  d_in[1];
    const float* behavior_counts = (const float*)d_in[2];
    const int*   target_user     = (const int*)  d_in[3];
    const float* similarity_vec  = (const float*)d_in[4];
    const float* user_emb_w      = (const float*)d_in[5];
    const float* item_emb_w      = (const float*)d_in[6];
    float* out = (float*)d_out;

    group_embedding_main<<<2 * G_, NTHREADS>>>(
        group_user, behavior_ids, behavior_counts, target_user,
        similarity_vec, user_emb_w, item_emb_w);
    group_embedding_reduce<<<(G_ * D_) / 256, 256>>>(out);
}

// round 11
// speedup vs baseline: 1.4821x; 1.4821x over previous
#include <cuda_runtime.h>

// Problem constants (from reference)
#define G_ 4096
#define U_ 50
#define M_ 20
#define D_ 64
#define S_ 64
#define FACTOR_ 0.5f

// R5 shape: 25 warps = 50 half-warp slots = one user per slot, single pass.
#define NWARPS 25
#define NTHREADS (NWARPS * 32)   // 800
#define SLOTS (NWARPS * 2)       // 50
#define MB 5                     // asm-forced gather batch depth

__global__ __launch_bounds__(NTHREADS, 2)
void group_embedding_kernel(const int*   __restrict__ group_user,      // [G,U]
                            const int*   __restrict__ behavior_ids,    // [G,U,M]
                            const float* __restrict__ behavior_counts, // [G,U,M]
                            const int*   __restrict__ target_user,     // [G]
                            const float* __restrict__ similarity_vec,  // [100000,S]
                            const float* __restrict__ user_emb_w,      // [100000,D]
                            const float* __restrict__ item_emb_w,      // [100000,D]
                            float*       __restrict__ out)             // [G,D]
{
    const int g    = blockIdx.x;
    const int tid  = threadIdx.x;
    const int warp = tid >> 5;
    const int lane = tid & 31;
    const int half = lane >> 4;     // which user of the warp's pair
    const int hl   = lane & 15;     // lane owns dims 4*hl..4*hl+3
    const int slot = warp * 2 + half;   // 0..49 == user index

    __shared__ __align__(16) float  partials[SLOTS][D_];  // 12.8KB
    __shared__ __align__(16) float  red[8][D_];           // 2KB
    __shared__ __align__(16) float2 wbeh[NWARPS][2 * M_]; // per-warp (id,count), 8KB

    // ---- Per-warp staging: this warp's 2 users' 40 (id,count) pairs ----
    {
        const int base = g * (U_ * M_) + warp * (2 * M_);
        wbeh[warp][lane] = make_float2(__int_as_float(behavior_ids[base + lane]),
                                       behavior_counts[base + lane]);
        if (lane < 8)
            wbeh[warp][32 + lane] =
                make_float2(__int_as_float(behavior_ids[base + 32 + lane]),
                            behavior_counts[base + 32 + lane]);
    }

    // This half-warp's user id (broadcast sector).
    const int uid = group_user[g * U_ + slot];

    // Early user-embedding load so it overlaps the gather chain.
    const float4 ue = *reinterpret_cast<const float4*>(
        user_emb_w + (size_t)uid * D_ + 4 * hl);

    // Target similarity vector.
    const int tgt = target_user[g];
    const float4 tsim = *reinterpret_cast<const float4*>(
        similarity_vec + (size_t)tgt * S_ + 4 * hl);

    // sim = FACTOR * dot(target_sim, other_sim), half-warp reduce.
    const float4 osim = *reinterpret_cast<const float4*>(
        similarity_vec + (size_t)uid * S_ + 4 * hl);
    float dot = tsim.x * osim.x + tsim.y * osim.y
              + tsim.z * osim.z + tsim.w * osim.w;
    #pragma unroll
    for (int o = 8; o; o >>= 1)
        dot += __shfl_xor_sync(0xffffffffu, dot, o);
    const float sim = FACTOR_ * dot;

    __syncwarp();   // own warp's wbeh slice ready

    // ---- Gather loop: 4 batches of MB=5 asm-forced independent LDG.128s.
    // Volatile asm loads are mutually ordered: ptxas must issue all 5 with
    // their 20 output registers live before the consuming FFMAs.
    float4 ub = make_float4(0.f, 0.f, 0.f, 0.f);
    const int bbase = half * M_;
    #pragma unroll
    for (int mb = 0; mb < M_; mb += MB) {
        float  c[MB];
        float4 e[MB];
        #pragma unroll
        for (int j = 0; j < MB; j++) {
            const float2 p = wbeh[warp][bbase + mb + j];
            c[j] = p.y;
            const float* addr =
                item_emb_w + (size_t)__float_as_int(p.x) * D_ + 4 * hl;
            asm volatile("ld.global.nc.v4.f32 {%0, %1, %2, %3}, [%4];"
                         : "=f"(e[j].x), "=f"(e[j].y), "=f"(e[j].z), "=f"(e[j].w)
                         : "l"(addr));
        }
        #pragma unroll
        for (int j = 0; j < MB; j++) {
            ub.x += e[j].x * c[j];
            ub.y += e[j].y * c[j];
            ub.z += e[j].z * c[j];
            ub.w += e[j].w * c[j];
        }
    }

    // Personalize with user embedding, weight by sim.
    float4 acc;
    acc.x = ub.x * ue.x * sim;
    acc.y = ub.y * ue.y * sim;
    acc.z = ub.z * ue.z * sim;
    acc.w = ub.w * ue.w * sim;

    *reinterpret_cast<float4*>(&partials[slot][4 * hl]) = acc;
    __syncthreads();

    // ---- Two-stage deterministic reduce over 50 slots ----
    if (tid < 512) {
        const int d = tid & 63;
        const int r = tid >> 6;      // 0..7
        float s = 0.f;
        #pragma unroll
        for (int p = r; p < SLOTS; p += 8)
            s += partials[p][d];
        red[r][d] = s;
    }
    __syncthreads();

    if (tid < D_) {
        float s = 0.f;
        #pragma unroll
        for (int r = 0; r < 8; r++)
            s += red[r][tid];
        out[(size_t)g * D_ + tid] = s;
    }
}

extern "C" void kernel_launch(void* const* d_in, const int* in_sizes, int n_in,
                              void* d_out, int out_size) {
    const int*   group_user      = (const int*)  d_in[0];
    const int*   behavior_ids    = (const int*)  d_in[1];
    const float* behavior_counts = (const float*)d_in[2];
    const int*   target_user     = (const int*)  d_in[3];
    const float* similarity_vec  = (const float*)d_in[4];
    const float* user_emb_w      = (const float*)d_in[5];
    const float* item_emb_w      = (const float*)d_in[6];
    float* out = (float*)d_out;

    group_embedding_kernel<<<G_, NTHREADS>>>(
        group_user, behavior_ids, behavior_counts, target_user,
        similarity_vec, user_emb_w, item_emb_w, out);
}

// round 12
// speedup vs baseline: 1.4967x; 1.0098x over previous
#include <cuda_runtime.h>

// Problem constants (from reference)
#define G_ 4096
#define U_ 50
#define M_ 20
#define D_ 64
#define S_ 64
#define FACTOR_ 0.5f

// R5 shape: 25 warps = 50 half-warp slots = one user per slot, single pass.
#define NWARPS 25
#define NTHREADS (NWARPS * 32)   // 800
#define SLOTS (NWARPS * 2)       // 50

__global__ __launch_bounds__(NTHREADS, 2)
void group_embedding_kernel(const int*   __restrict__ group_user,      // [G,U]
                            const int*   __restrict__ behavior_ids,    // [G,U,M]
                            const float* __restrict__ behavior_counts, // [G,U,M]
                            const int*   __restrict__ target_user,     // [G]
                            const float* __restrict__ similarity_vec,  // [100000,S]
                            const float* __restrict__ user_emb_w,      // [100000,D]
                            const float* __restrict__ item_emb_w,      // [100000,D]
                            float*       __restrict__ out)             // [G,D]
{
    const int g    = blockIdx.x;
    const int tid  = threadIdx.x;
    const int warp = tid >> 5;
    const int lane = tid & 31;
    const int half = lane >> 4;     // which user of the warp's pair
    const int hl   = lane & 15;     // lane owns dims 4*hl..4*hl+3
    const int slot = warp * 2 + half;   // 0..49 == user index

    __shared__ __align__(16) float  partials[SLOTS][D_];  // 12.8KB
    __shared__ __align__(16) float  red[8][D_];           // 2KB
    __shared__ __align__(16) float2 wbeh[NWARPS][2 * M_]; // per-warp (id,count), 8KB

    // ---- Per-warp staging: this warp's 2 users' 40 (id,count) pairs ----
    {
        const int base = g * (U_ * M_) + warp * (2 * M_);
        wbeh[warp][lane] = make_float2(__int_as_float(behavior_ids[base + lane]),
                                       behavior_counts[base + lane]);
        if (lane < 8)
            wbeh[warp][32 + lane] =
                make_float2(__int_as_float(behavior_ids[base + 32 + lane]),
                            behavior_counts[base + 32 + lane]);
    }
    __syncwarp();   // own warp's wbeh slice ready

    // ---- Gather loop FIRST, with minimal register residency.
    // Each iteration reads one LDS.128 (two (id,count) pairs) and issues two
    // independent LDG.128 gathers. Nothing else is live across the loop.
    const float4* pf4 = reinterpret_cast<const float4*>(&wbeh[warp][half * M_]);
    float4 ub = make_float4(0.f, 0.f, 0.f, 0.f);
    #pragma unroll
    for (int mb = 0; mb < M_ / 2; mb++) {
        const float4 p = pf4[mb];     // (id0, c0, id1, c1)
        const float4 e0 = *reinterpret_cast<const float4*>(
            item_emb_w + (size_t)__float_as_int(p.x) * D_ + 4 * hl);
        const float4 e1 = *reinterpret_cast<const float4*>(
            item_emb_w + (size_t)__float_as_int(p.z) * D_ + 4 * hl);
        ub.x += e0.x * p.y;  ub.y += e0.y * p.y;
        ub.z += e0.z * p.y;  ub.w += e0.w * p.y;
        ub.x += e1.x * p.w;  ub.y += e1.y * p.w;
        ub.z += e1.z * p.w;  ub.w += e1.w * p.w;
    }

    // ---- Now the per-user metadata loads (after the hot loop).
    const int uid = group_user[g * U_ + slot];

    const float4 ue = *reinterpret_cast<const float4*>(
        user_emb_w + (size_t)uid * D_ + 4 * hl);

    const int tgt = target_user[g];
    const float4 tsim = *reinterpret_cast<const float4*>(
        similarity_vec + (size_t)tgt * S_ + 4 * hl);
    const float4 osim = *reinterpret_cast<const float4*>(
        similarity_vec + (size_t)uid * S_ + 4 * hl);
    float dot = tsim.x * osim.x + tsim.y * osim.y
              + tsim.z * osim.z + tsim.w * osim.w;
    #pragma unroll
    for (int o = 8; o; o >>= 1)
        dot += __shfl_xor_sync(0xffffffffu, dot, o);
    const float sim = FACTOR_ * dot;

    // Personalize with user embedding, weight by sim.
    float4 acc;
    acc.x = ub.x * ue.x * sim;
    acc.y = ub.y * ue.y * sim;
    acc.z = ub.z * ue.z * sim;
    acc.w = ub.w * ue.w * sim;

    *reinterpret_cast<float4*>(&partials[slot][4 * hl]) = acc;
    __syncthreads();

    // ---- Two-stage deterministic reduce over 50 slots ----
    if (tid < 512) {
        const int d = tid & 63;
        const int r = tid >> 6;      // 0..7
        float s = 0.f;
        #pragma unroll
        for (int p = r; p < SLOTS; p += 8)
            s += partials[p][d];
        red[r][d] = s;
    }
    __syncthreads();

    if (tid < D_) {
        float s = 0.f;
        #pragma unroll
        for (int r = 0; r < 8; r++)
            s += red[r][tid];
        out[(size_t)g * D_ + tid] = s;
    }
}

extern "C" void kernel_launch(void* const* d_in, const int* in_sizes, int n_in,
                              void* d_out, int out_size) {
    const int*   group_user      = (const int*)  d_in[0];
    const int*   behavior_ids    = (const int*)  d_in[1];
    const float* behavior_counts = (const float*)d_in[2];
    const int*   target_user     = (const int*)  d_in[3];
    const float* similarity_vec  = (const float*)d_in[4];
    const float* user_emb_w      = (const float*)d_in[5];
    const float* item_emb_w      = (const float*)d_in[6];
    float* out = (float*)d_out;

    group_embedding_kernel<<<G_, NTHREADS>>>(
        group_user, behavior_ids, behavior_counts, target_user,
        similarity_vec, user_emb_w, item_emb_w, out);
}